// round 1
// baseline (speedup 1.0000x reference)
#include <cuda_runtime.h>
#include <cstdint>

#define COLS      32768
#define NTHREADS  1024
#define NCHUNK    (COLS / (NTHREADS * 4))   // 8 float4 chunks per thread
#define CAP       4096                       // candidate capacity (mean ~745)
#define ECAP      1024                       // threshold-bin capacity (mean ~25)
#define NBINS     2048                       // digits (bits>>19) - 0x800 for bits >= 0x40000000

__device__ __forceinline__ unsigned block_reduce_sum(unsigned v, unsigned* s_red) {
    const int tid = threadIdx.x;
    __syncthreads();  // protect s_red reuse across calls
    #pragma unroll
    for (int o = 16; o > 0; o >>= 1) v += __shfl_down_sync(0xffffffffu, v, o);
    if ((tid & 31) == 0) s_red[tid >> 5] = v;
    __syncthreads();
    if (tid < 32) {
        unsigned r = s_red[tid];
        #pragma unroll
        for (int o = 16; o > 0; o >>= 1) r += __shfl_down_sync(0xffffffffu, r, o);
        if (tid == 0) s_red[0] = r;
    }
    __syncthreads();
    return s_red[0];
}

__global__ void __launch_bounds__(NTHREADS, 1)
topk_rows_kernel(const float* __restrict__ x, const int* __restrict__ kptr,
                 float* __restrict__ out, int rows)
{
    __shared__ unsigned       s_hist[NBINS];      // 8 KB
    __shared__ float          s_val[CAP];         // 16 KB
    __shared__ unsigned short s_colbuf[CAP];      // 8 KB
    __shared__ float          e_val[ECAP];        // 4 KB
    __shared__ unsigned short e_col[ECAP];        // 2 KB
    __shared__ unsigned       s_red[32];
    __shared__ unsigned       s_cnt, s_maxd, s_ecnt, s_D, s_m;

    const int row = blockIdx.x;
    if (row >= rows) return;
    const int tid  = threadIdx.x;
    const int lane = tid & 31;
    const int K    = __ldg(kptr);

    const float* __restrict__ xr   = x   + (size_t)row * COLS;
    float*       __restrict__ orow = out + (size_t)row * COLS;

    if (tid == 0) { s_cnt = 0u; s_maxd = 0u; s_ecnt = 0u; }
    for (int i = tid; i < NBINS; i += NTHREADS) s_hist[i] = 0u;
    __syncthreads();

    // ------------------------------------------------------------------
    // Pass 1 (the only full-row memory pass):
    //   - stream-read row (evict-first)
    //   - stream-write zeros to the entire output row
    //   - gather candidates (value >= 2.0f) + histogram their bit-digits
    // ------------------------------------------------------------------
    #pragma unroll
    for (int c = 0; c < NCHUNK; c++) {
        const int col0 = c * (NTHREADS * 4) + tid * 4;
        const float4 v = __ldcs(reinterpret_cast<const float4*>(xr + col0));
        __stcs(reinterpret_cast<float4*>(orow + col0), make_float4(0.f, 0.f, 0.f, 0.f));
        #pragma unroll
        for (int j = 0; j < 4; j++) {
            const float f = (j == 0) ? v.x : (j == 1) ? v.y : (j == 2) ? v.z : v.w;
            const int   b = __float_as_int(f);
            const bool cand = (b >= 0x40000000);           // f >= 2.0f (sign excluded via signed cmp)
            const unsigned mask = __ballot_sync(0xffffffffu, cand);
            if (mask) {
                const int leader = __ffs(mask) - 1;
                unsigned base = 0u;
                if (lane == leader) base = atomicAdd(&s_cnt, (unsigned)__popc(mask));
                base = __shfl_sync(0xffffffffu, base, leader);
                if (cand) {
                    const unsigned p = base + (unsigned)__popc(mask & ((1u << lane) - 1u));
                    if (p < CAP) {
                        s_val[p]    = f;
                        s_colbuf[p] = (unsigned short)(col0 + j);
                        const unsigned d = ((unsigned)b >> 19) - 0x800u;   // in [0, NBINS)
                        atomicAdd(&s_hist[d], 1u);
                        atomicMax(&s_maxd, d);
                    }
                }
            }
        }
    }
    __syncthreads();

    const unsigned n = s_cnt;
    bool fast = (K > 0) && (n >= (unsigned)K) && (n <= CAP);

    if (fast) {
        // -------- warp-0: walk bins from the top to find bin D and quota m --------
        if (tid < 32) {
            int rem = K;
            int hi  = (int)s_maxd;
            for (;;) {
                const int bin  = hi - lane;
                unsigned cnt   = (bin >= 0) ? s_hist[bin] : 0u;
                unsigned cum   = cnt;
                #pragma unroll
                for (int o = 1; o < 32; o <<= 1) {
                    unsigned t = __shfl_up_sync(0xffffffffu, cum, o);
                    if (lane >= o) cum += t;
                }
                const unsigned crossed = __ballot_sync(0xffffffffu, cum >= (unsigned)rem);
                if (crossed) {
                    const int cl = __ffs(crossed) - 1;
                    const unsigned cumprev = __shfl_sync(0xffffffffu, cum - cnt, cl);
                    if (lane == 0) { s_D = (unsigned)(hi - cl); s_m = (unsigned)rem - cumprev; }
                    break;
                }
                rem -= (int)__shfl_sync(0xffffffffu, cum, 31);
                hi  -= 32;   // n >= K guarantees a crossing before hi underflows meaningfully
            }
        }
        __syncthreads();
        const unsigned D = s_D;

        // -------- gather threshold-bin entries (decide fallback before writing) --------
        for (unsigned i = tid; i < n; i += NTHREADS) {
            const unsigned d = (__float_as_uint(s_val[i]) >> 19) - 0x800u;
            if (d == D) {
                const unsigned p = atomicAdd(&s_ecnt, 1u);
                if (p < ECAP) { e_val[p] = s_val[i]; e_col[p] = s_colbuf[i]; }
            }
        }
        __syncthreads();
        if (s_ecnt > ECAP) fast = false;   // pathological ties -> generic path

        if (fast) {
            // strict winners (digit > D): provably in the exact top-K
            for (unsigned i = tid; i < n; i += NTHREADS) {
                const float f = s_val[i];
                const unsigned d = (__float_as_uint(f) >> 19) - 0x800u;
                if (d > D) orow[s_colbuf[i]] = f;
            }
            // bin-D: exact top-m by (value desc, index asc) == jax top_k tie order
            const unsigned ne = s_ecnt;
            const unsigned m  = s_m;
            if (tid < 32) {
                for (unsigned i = (unsigned)lane; i < ne; i += 32u) {
                    const unsigned bi = __float_as_uint(e_val[i]);
                    const unsigned ci = e_col[i];
                    unsigned rank = 0;
                    for (unsigned j = 0; j < ne; j++) {
                        const unsigned bj = __float_as_uint(e_val[j]);
                        const unsigned cj = e_col[j];
                        rank += (unsigned)((bj > bi) || (bj == bi && cj < ci));
                    }
                    if (rank < m) orow[ci] = e_val[i];
                }
            }
            return;
        }
    }

    // ======================================================================
    // Generic exact fallback (statistically never taken for this input):
    // binary search the K-th largest positive-bit key by block counting,
    // re-reading the row from L2. Zeros were already written in pass 1.
    // ======================================================================
    {
        const int kk = (K < COLS) ? K : COLS;
        if (kk <= 0) return;

        auto count_ge = [&](unsigned t) -> unsigned {
            unsigned c = 0;
            for (int cc = 0; cc < NCHUNK; cc++) {
                const int col0 = cc * (NTHREADS * 4) + tid * 4;
                const float4 v = *reinterpret_cast<const float4*>(xr + col0);
                #pragma unroll
                for (int j = 0; j < 4; j++) {
                    const float f = (j == 0) ? v.x : (j == 1) ? v.y : (j == 2) ? v.z : v.w;
                    const int   b = __float_as_int(f);
                    const unsigned key = (b > 0) ? (unsigned)b : 0u;
                    c += (unsigned)(key >= t);
                }
            }
            return block_reduce_sum(c, s_red);
        };

        const unsigned cpos = count_ge(1u);
        if (cpos <= (unsigned)kk) {
            // fewer positives than k: reference keeps all of them (+zeros)
            for (int cc = 0; cc < NCHUNK; cc++) {
                const int col0 = cc * (NTHREADS * 4) + tid * 4;
                const float4 v = *reinterpret_cast<const float4*>(xr + col0);
                #pragma unroll
                for (int j = 0; j < 4; j++) {
                    const float f = (j == 0) ? v.x : (j == 1) ? v.y : (j == 2) ? v.z : v.w;
                    if (__float_as_int(f) > 0) orow[col0 + j] = f;
                }
            }
            return;
        }

        unsigned lo = 1u, hi = 0x7F800000u;     // f(lo) >= kk, f(hi) < kk
        while (hi - lo > 1u) {
            const unsigned mid = lo + (hi - lo) / 2u;
            if (count_ge(mid) >= (unsigned)kk) lo = mid; else hi = mid;
        }
        const unsigned T = lo;
        const unsigned g = count_ge(T + 1u);    // strictly greater than T
        const unsigned m = (unsigned)kk - g;

        if (tid == 0) s_ecnt = 0u;
        __syncthreads();
        for (int cc = 0; cc < NCHUNK; cc++) {
            const int col0 = cc * (NTHREADS * 4) + tid * 4;
            const float4 v = *reinterpret_cast<const float4*>(xr + col0);
            #pragma unroll
            for (int j = 0; j < 4; j++) {
                const float f = (j == 0) ? v.x : (j == 1) ? v.y : (j == 2) ? v.z : v.w;
                const int   b = __float_as_int(f);
                const unsigned key = (b > 0) ? (unsigned)b : 0u;
                if (key > T) {
                    orow[col0 + j] = f;
                } else if (key == T) {
                    const unsigned p = atomicAdd(&s_ecnt, 1u);
                    if (p < ECAP) { e_val[p] = f; e_col[p] = (unsigned short)(col0 + j); }
                }
            }
        }
        __syncthreads();
        const unsigned ne = (s_ecnt < ECAP) ? s_ecnt : ECAP;
        if (tid < 32) {
            for (unsigned i = (unsigned)lane; i < ne; i += 32u) {
                const unsigned ci = e_col[i];
                unsigned rank = 0;
                for (unsigned j = 0; j < ne; j++) rank += (unsigned)(e_col[j] < ci);  // equal values: ties by index
                if (rank < m) orow[ci] = e_val[i];
            }
        }
    }
}

extern "C" void kernel_launch(void* const* d_in, const int* in_sizes, int n_in,
                              void* d_out, int out_size)
{
    const float* x = (const float*)d_in[0];
    const int*   k = (const int*)d_in[1];       // scalar k on device (metadata order: x, k)
    float*       o = (float*)d_out;
    const int rows = in_sizes[0] / COLS;
    topk_rows_kernel<<<rows, NTHREADS>>>(x, k, o, rows);
}

// round 2
// speedup vs baseline: 1.5677x; 1.5677x over previous
#include <cuda_runtime.h>
#include <cstdint>

#define COLS        32768
#define NT          256
#define NCHUNK      (COLS / (NT * 4))      // 32 float4 chunks per thread
#define CAP         1024                   // candidate capacity (mean ~247, sigma ~16)
#define ECAP        512                    // threshold-bin capacity (mean ~25)
#define NBINS       2048                   // digit = (bits>>19) - 0x800 for bits >= 2.0f
#define THRESH_BITS 0x401C0000             // 2.4375f as int bits

__device__ __forceinline__ unsigned block_reduce_sum(unsigned v, unsigned* s_red) {
    const int tid = threadIdx.x;
    __syncthreads();                        // protect s_red reuse across calls
    #pragma unroll
    for (int o = 16; o > 0; o >>= 1) v += __shfl_down_sync(0xffffffffu, v, o);
    if ((tid & 31) == 0) s_red[tid >> 5] = v;
    __syncthreads();
    if (tid < 32) {
        unsigned r = (tid < NT / 32) ? s_red[tid] : 0u;
        #pragma unroll
        for (int o = 16; o > 0; o >>= 1) r += __shfl_down_sync(0xffffffffu, r, o);
        if (tid == 0) s_red[0] = r;
    }
    __syncthreads();
    return s_red[0];
}

__global__ void __launch_bounds__(NT, 5)
topk_rows_kernel(const float* __restrict__ x, const int* __restrict__ kptr,
                 float* __restrict__ out, int rows)
{
    __shared__ unsigned       s_hist[NBINS];      // 8 KB
    __shared__ float          s_val[CAP];         // 4 KB
    __shared__ unsigned short s_col[CAP];         // 2 KB
    __shared__ float          e_val[ECAP];        // 2 KB
    __shared__ unsigned short e_col[ECAP];        // 1 KB
    __shared__ unsigned       s_red[NT / 32];
    __shared__ unsigned       s_cnt, s_maxd, s_ecnt, s_D, s_m;

    const int row = blockIdx.x;
    if (row >= rows) return;
    const int tid  = threadIdx.x;
    const int lane = tid & 31;
    const int K    = __ldg(kptr);

    const float* __restrict__ xr   = x   + (size_t)row * COLS;
    float*       __restrict__ orow = out + (size_t)row * COLS;

    if (tid == 0) { s_cnt = 0u; s_maxd = 0u; s_ecnt = 0u; }
    for (int i = tid; i < NBINS; i += NT) s_hist[i] = 0u;
    __syncthreads();

    // ------------------------------------------------------------------
    // Pass 1 (the only full-row memory pass): stream-read + zero-write,
    // group-test 4 elements with integer max, rare direct push to SMEM.
    // ------------------------------------------------------------------
    const float4* __restrict__ xv = reinterpret_cast<const float4*>(xr);
    float4*       __restrict__ ov = reinterpret_cast<float4*>(orow);
    const float4 z4 = make_float4(0.f, 0.f, 0.f, 0.f);

    #pragma unroll 4
    for (int c = 0; c < NCHUNK; c++) {
        const int idx = c * NT + tid;              // float4 index within row
        const float4 v = __ldcs(&xv[idx]);
        ov[idx] = z4;                              // default policy: lines linger in L2 for scatter
        const int b0 = __float_as_int(v.x);
        const int b1 = __float_as_int(v.y);
        const int b2 = __float_as_int(v.z);
        const int b3 = __float_as_int(v.w);
        const int gm = max(max(b0, b1), max(b2, b3));
        if (gm >= THRESH_BITS) {                   // ~62% of warp-chunk iterations (warp-level)
            const int col0 = idx * 4;
            #pragma unroll
            for (int j = 0; j < 4; j++) {
                const int b = (j == 0) ? b0 : (j == 1) ? b1 : (j == 2) ? b2 : b3;
                if (b >= THRESH_BITS) {
                    const unsigned p = atomicAdd(&s_cnt, 1u);
                    if (p < CAP) {
                        s_val[p] = __int_as_float(b);
                        s_col[p] = (unsigned short)(col0 + j);
                    }
                }
            }
        }
    }
    __syncthreads();

    const unsigned n = s_cnt;
    bool fast = (K > 0) && (n >= (unsigned)K) && (n <= CAP);

    if (fast) {
        // -------- build digit histogram from the compacted candidates --------
        for (unsigned i = tid; i < n; i += NT) {
            const unsigned d = (__float_as_uint(s_val[i]) >> 19) - 0x800u;
            atomicAdd(&s_hist[d], 1u);
            atomicMax(&s_maxd, d);
        }
        __syncthreads();

        // -------- warp-0: walk bins from the top: find bin D and quota m --------
        if (tid < 32) {
            int rem = K;
            int hi  = (int)s_maxd;
            for (;;) {
                const int bin  = hi - lane;
                unsigned cnt   = (bin >= 0) ? s_hist[bin] : 0u;
                unsigned cum   = cnt;
                #pragma unroll
                for (int o = 1; o < 32; o <<= 1) {
                    unsigned t = __shfl_up_sync(0xffffffffu, cum, o);
                    if (lane >= o) cum += t;
                }
                const unsigned crossed = __ballot_sync(0xffffffffu, cum >= (unsigned)rem);
                if (crossed) {
                    const int cl = __ffs(crossed) - 1;
                    const unsigned cumprev = __shfl_sync(0xffffffffu, cum - cnt, cl);
                    if (lane == 0) { s_D = (unsigned)(hi - cl); s_m = (unsigned)rem - cumprev; }
                    break;
                }
                rem -= (int)__shfl_sync(0xffffffffu, cum, 31);
                hi  -= 32;                     // n >= K guarantees a crossing
            }
        }
        __syncthreads();
        const unsigned D = s_D;

        // -------- gather threshold-bin entries (validate before writing) --------
        for (unsigned i = tid; i < n; i += NT) {
            const unsigned d = (__float_as_uint(s_val[i]) >> 19) - 0x800u;
            if (d == D) {
                const unsigned p = atomicAdd(&s_ecnt, 1u);
                if (p < ECAP) { e_val[p] = s_val[i]; e_col[p] = s_col[i]; }
            }
        }
        __syncthreads();
        if (s_ecnt > ECAP) fast = false;       // pathological ties -> generic path

        if (fast) {
            // strict winners (digit > D): provably in the exact top-K
            for (unsigned i = tid; i < n; i += NT) {
                const float f = s_val[i];
                const unsigned d = (__float_as_uint(f) >> 19) - 0x800u;
                if (d > D) orow[s_col[i]] = f;
            }
            // bin-D: exact top-m by (value desc, index asc) == jax top_k tie order
            const unsigned ne = s_ecnt;
            const unsigned m  = s_m;
            if (tid < 32) {
                for (unsigned i = (unsigned)lane; i < ne; i += 32u) {
                    const unsigned bi = __float_as_uint(e_val[i]);
                    const unsigned ci = e_col[i];
                    unsigned rank = 0;
                    for (unsigned j = 0; j < ne; j++) {
                        const unsigned bj = __float_as_uint(e_val[j]);
                        const unsigned cj = e_col[j];
                        rank += (unsigned)((bj > bi) || (bj == bi && cj < ci));
                    }
                    if (rank < m) orow[ci] = e_val[i];
                }
            }
            return;
        }
    }

    // ======================================================================
    // Generic exact fallback (statistically never taken for this input):
    // binary search the K-th largest positive-bit key by block counting.
    // Zeros were already written in pass 1.
    // ======================================================================
    {
        const int kk = (K < COLS) ? K : COLS;
        if (kk <= 0) return;

        auto count_ge = [&](unsigned t) -> unsigned {
            unsigned c = 0;
            for (int cc = 0; cc < NCHUNK; cc++) {
                const int idx = cc * NT + tid;
                const float4 v = xv[idx];
                #pragma unroll
                for (int j = 0; j < 4; j++) {
                    const float f = (j == 0) ? v.x : (j == 1) ? v.y : (j == 2) ? v.z : v.w;
                    const int   b = __float_as_int(f);
                    const unsigned key = (b > 0) ? (unsigned)b : 0u;
                    c += (unsigned)(key >= t);
                }
            }
            return block_reduce_sum(c, s_red);
        };

        const unsigned cpos = count_ge(1u);
        if (cpos <= (unsigned)kk) {
            // fewer positives than k: reference keeps all of them (+zeros)
            for (int cc = 0; cc < NCHUNK; cc++) {
                const int idx = cc * NT + tid;
                const float4 v = xv[idx];
                #pragma unroll
                for (int j = 0; j < 4; j++) {
                    const float f = (j == 0) ? v.x : (j == 1) ? v.y : (j == 2) ? v.z : v.w;
                    if (__float_as_int(f) > 0) orow[idx * 4 + j] = f;
                }
            }
            return;
        }

        unsigned lo = 1u, hi = 0x7F800000u;     // count(lo) >= kk, count(hi) < kk
        while (hi - lo > 1u) {
            const unsigned mid = lo + (hi - lo) / 2u;
            if (count_ge(mid) >= (unsigned)kk) lo = mid; else hi = mid;
        }
        const unsigned T = lo;
        const unsigned g = count_ge(T + 1u);    // strictly greater than T
        const unsigned m = (unsigned)kk - g;

        if (tid == 0) s_ecnt = 0u;
        __syncthreads();
        for (int cc = 0; cc < NCHUNK; cc++) {
            const int idx = cc * NT + tid;
            const float4 v = xv[idx];
            #pragma unroll
            for (int j = 0; j < 4; j++) {
                const float f = (j == 0) ? v.x : (j == 1) ? v.y : (j == 2) ? v.z : v.w;
                const int   b = __float_as_int(f);
                const unsigned key = (b > 0) ? (unsigned)b : 0u;
                if (key > T) {
                    orow[idx * 4 + j] = f;
                } else if (key == T) {
                    const unsigned p = atomicAdd(&s_ecnt, 1u);
                    if (p < ECAP) { e_val[p] = f; e_col[p] = (unsigned short)(idx * 4 + j); }
                }
            }
        }
        __syncthreads();
        const unsigned ne = (s_ecnt < ECAP) ? s_ecnt : ECAP;
        if (tid < 32) {
            for (unsigned i = (unsigned)lane; i < ne; i += 32u) {
                const unsigned ci = e_col[i];
                unsigned rank = 0;
                for (unsigned j = 0; j < ne; j++) rank += (unsigned)(e_col[j] < ci); // equal values: tie by index
                if (rank < m) orow[ci] = e_val[i];
            }
        }
    }
}

extern "C" void kernel_launch(void* const* d_in, const int* in_sizes, int n_in,
                              void* d_out, int out_size)
{
    const float* x = (const float*)d_in[0];
    const int*   k = (const int*)d_in[1];
    float*       o = (float*)d_out;
    const int rows = in_sizes[0] / COLS;
    topk_rows_kernel<<<rows, NT>>>(x, k, o, rows);
}

// round 3
// speedup vs baseline: 1.8602x; 1.1866x over previous
#include <cuda_runtime.h>
#include <cstdint>

#define COLS         32768
#define NT           256
#define CAP          1024                  // candidate capacity (mean ~247)
#define ECAP         512                   // threshold-bin capacity (mean ~25)
#define NBINS        2048                  // digit = (bits>>19) - 0x800
#define THRESH_BITS  0x401C0000            // 2.4375f
#define STAGES       4
#define STAGE_BYTES  16384
#define STAGE_F4     (STAGE_BYTES / 16)    // 1024 float4 per stage
#define CHUNKS       (COLS * 4 / STAGE_BYTES)   // 8 stages per row
#define F4PT         (STAGE_F4 / NT)       // 4 float4 per thread per stage
#define ZERO_BYTES   8192
#define NZSTORE      (COLS * 4 / ZERO_BYTES)    // 16 zero stores per row
#define DYN_SMEM     (STAGES * STAGE_BYTES + ZERO_BYTES)
#define NCHUNK_G     (COLS / (NT * 4))     // fallback: 32 float4 per thread

__device__ __forceinline__ uint32_t smem_u32(const void* p) {
    uint32_t a;
    asm("{ .reg .u64 t; cvta.to.shared.u64 t, %1; cvt.u32.u64 %0, t; }" : "=r"(a) : "l"(p));
    return a;
}
__device__ __forceinline__ void mbar_init(uint32_t bar, unsigned cnt) {
    asm volatile("mbarrier.init.shared.b64 [%0], %1;" :: "r"(bar), "r"(cnt) : "memory");
}
__device__ __forceinline__ void mbar_expect_tx(uint32_t bar, unsigned bytes) {
    asm volatile("mbarrier.arrive.expect_tx.shared.b64 _, [%0], %1;" :: "r"(bar), "r"(bytes) : "memory");
}
__device__ __forceinline__ void mbar_wait(uint32_t bar, unsigned parity) {
    asm volatile(
        "{\n\t.reg .pred P;\n"
        "W%=:\n\t"
        "mbarrier.try_wait.parity.acquire.cta.shared::cta.b64 P, [%0], %1, 0x989680;\n\t"
        "@!P bra W%=;\n\t}"
        :: "r"(bar), "r"(parity) : "memory");
}
__device__ __forceinline__ void bulk_g2s(uint32_t dst, const void* src, unsigned bytes, uint32_t bar) {
    asm volatile("cp.async.bulk.shared::cluster.global.mbarrier::complete_tx::bytes [%0], [%1], %2, [%3];"
                 :: "r"(dst), "l"(src), "r"(bytes), "r"(bar) : "memory");
}
__device__ __forceinline__ void bulk_s2g(void* dst, uint32_t src, unsigned bytes) {
    asm volatile("cp.async.bulk.global.shared::cta.bulk_group [%0], [%1], %2;"
                 :: "l"(dst), "r"(src), "r"(bytes) : "memory");
}

__device__ __forceinline__ unsigned block_reduce_sum(unsigned v, unsigned* s_red) {
    const int tid = threadIdx.x;
    __syncthreads();
    #pragma unroll
    for (int o = 16; o > 0; o >>= 1) v += __shfl_down_sync(0xffffffffu, v, o);
    if ((tid & 31) == 0) s_red[tid >> 5] = v;
    __syncthreads();
    if (tid < 32) {
        unsigned r = (tid < NT / 32) ? s_red[tid] : 0u;
        #pragma unroll
        for (int o = 16; o > 0; o >>= 1) r += __shfl_down_sync(0xffffffffu, r, o);
        if (tid == 0) s_red[0] = r;
    }
    __syncthreads();
    return s_red[0];
}

extern __shared__ char dsm[];

__global__ void __launch_bounds__(NT, 2)
topk_rows_kernel(const float* __restrict__ x, const int* __restrict__ kptr,
                 float* __restrict__ out, int rows)
{
    __shared__ unsigned       s_hist[NBINS];
    __shared__ float          s_val[CAP];
    __shared__ unsigned short s_col[CAP];
    __shared__ float          e_val[ECAP];
    __shared__ unsigned short e_col[ECAP];
    __shared__ unsigned       s_red[NT / 32];
    __shared__ unsigned       s_cnt, s_maxd, s_ecnt, s_D, s_m;
    __shared__ __align__(8) unsigned long long s_bar[STAGES];

    const int tid  = threadIdx.x;
    const int lane = tid & 31;
    const int K    = __ldg(kptr);

    const uint32_t stage0   = smem_u32(dsm);
    const uint32_t zero_sm  = stage0 + STAGES * STAGE_BYTES;
    const uint32_t bar0     = smem_u32(&s_bar[0]);

    // init zero buffer + barriers, once
    float4* zb = reinterpret_cast<float4*>(dsm + STAGES * STAGE_BYTES);
    for (int i = tid; i < ZERO_BYTES / 16; i += NT) zb[i] = make_float4(0.f, 0.f, 0.f, 0.f);
    if (tid == 0)
        for (int i = 0; i < STAGES; i++) mbar_init(bar0 + 8u * i, 1u);
    asm volatile("fence.proxy.async;" ::: "memory");
    __syncthreads();

    // stage g (global counter) -> (row, chunk)
    const int my_rows = (rows > (int)blockIdx.x) ? ((rows - 1 - (int)blockIdx.x) / (int)gridDim.x + 1) : 0;
    const int total_stages = my_rows * CHUNKS;

    auto stage_src = [&](int g) -> const void* {
        const size_t row = (size_t)blockIdx.x + (size_t)(g >> 3) * gridDim.x;
        return (const void*)(x + row * COLS + (size_t)(g & 7) * (STAGE_BYTES / 4));
    };

    // prologue: fill the pipeline
    if (tid == 0) {
        const int np = total_stages < STAGES ? total_stages : STAGES;
        for (int g = 0; g < np; g++) {
            mbar_expect_tx(bar0 + 8u * (g & 3), STAGE_BYTES);
            bulk_g2s(stage0 + (uint32_t)(g & 3) * STAGE_BYTES, stage_src(g), STAGE_BYTES, bar0 + 8u * (g & 3));
        }
    }

    int g = 0;
    for (int row = blockIdx.x; row < rows; row += gridDim.x) {
        const float* __restrict__ xr   = x   + (size_t)row * COLS;
        float*       __restrict__ orow = out + (size_t)row * COLS;
        const float4* __restrict__ xv  = reinterpret_cast<const float4*>(xr);

        // per-row init + launch the zero-fill of the output row (engine-driven)
        for (int i = tid; i < NBINS; i += NT) s_hist[i] = 0u;
        if (tid == 0) {
            s_cnt = 0u; s_maxd = 0u; s_ecnt = 0u;
            for (int i = 0; i < NZSTORE; i++)
                bulk_s2g(orow + i * (ZERO_BYTES / 4), zero_sm, ZERO_BYTES);
            asm volatile("cp.async.bulk.commit_group;" ::: "memory");
        }
        __syncthreads();

        // ---- scan 8 staged chunks from SMEM ----
        for (int ch = 0; ch < CHUNKS; ch++, g++) {
            const int slot    = g & 3;
            const unsigned ph = (unsigned)((g >> 2) & 1);
            mbar_wait(bar0 + 8u * slot, ph);
            const float4* sv = reinterpret_cast<const float4*>(dsm + slot * STAGE_BYTES);
            const int colbase = ch * (STAGE_BYTES / 4);
            #pragma unroll
            for (int j = 0; j < F4PT; j++) {
                const int fi = j * NT + tid;
                const float4 v = sv[fi];
                const int b0 = __float_as_int(v.x);
                const int b1 = __float_as_int(v.y);
                const int b2 = __float_as_int(v.z);
                const int b3 = __float_as_int(v.w);
                const int gm = max(max(b0, b1), max(b2, b3));
                if (gm >= THRESH_BITS) {
                    const int c0 = colbase + fi * 4;
                    #pragma unroll
                    for (int e = 0; e < 4; e++) {
                        const int b = (e == 0) ? b0 : (e == 1) ? b1 : (e == 2) ? b2 : b3;
                        if (b >= THRESH_BITS) {
                            const unsigned p = atomicAdd(&s_cnt, 1u);
                            if (p < CAP) { s_val[p] = __int_as_float(b); s_col[p] = (unsigned short)(c0 + e); }
                        }
                    }
                }
            }
            __syncthreads();                     // all threads done with this slot
            if (tid == 0 && g + STAGES < total_stages) {
                mbar_expect_tx(bar0 + 8u * slot, STAGE_BYTES);
                bulk_g2s(stage0 + (uint32_t)slot * STAGE_BYTES, stage_src(g + STAGES), STAGE_BYTES, bar0 + 8u * slot);
            }
        }

        // zero-fill must be durable before scatter
        if (tid == 0) asm volatile("cp.async.bulk.wait_group 0;" ::: "memory");
        __syncthreads();

        // ---------------- selection (exact) ----------------
        const unsigned n = s_cnt;
        bool fast = (K > 0) && (n >= (unsigned)K) && (n <= CAP);
        bool done = false;

        if (fast) {
            for (unsigned i = tid; i < n; i += NT) {
                const unsigned d = (__float_as_uint(s_val[i]) >> 19) - 0x800u;
                atomicAdd(&s_hist[d], 1u);
                atomicMax(&s_maxd, d);
            }
            __syncthreads();

            if (tid < 32) {
                int rem = K;
                int hi  = (int)s_maxd;
                for (;;) {
                    const int bin = hi - lane;
                    unsigned cnt  = (bin >= 0) ? s_hist[bin] : 0u;
                    unsigned cum  = cnt;
                    #pragma unroll
                    for (int o = 1; o < 32; o <<= 1) {
                        unsigned t = __shfl_up_sync(0xffffffffu, cum, o);
                        if (lane >= o) cum += t;
                    }
                    const unsigned crossed = __ballot_sync(0xffffffffu, cum >= (unsigned)rem);
                    if (crossed) {
                        const int cl = __ffs(crossed) - 1;
                        const unsigned cumprev = __shfl_sync(0xffffffffu, cum - cnt, cl);
                        if (lane == 0) { s_D = (unsigned)(hi - cl); s_m = (unsigned)rem - cumprev; }
                        break;
                    }
                    rem -= (int)__shfl_sync(0xffffffffu, cum, 31);
                    hi  -= 32;                    // n >= K guarantees a crossing
                }
            }
            __syncthreads();
            const unsigned D = s_D;

            for (unsigned i = tid; i < n; i += NT) {
                const unsigned d = (__float_as_uint(s_val[i]) >> 19) - 0x800u;
                if (d == D) {
                    const unsigned p = atomicAdd(&s_ecnt, 1u);
                    if (p < ECAP) { e_val[p] = s_val[i]; e_col[p] = s_col[i]; }
                }
            }
            __syncthreads();

            if (s_ecnt <= ECAP) {
                // strict winners (digit > D): provably in the exact top-K
                for (unsigned i = tid; i < n; i += NT) {
                    const float f = s_val[i];
                    const unsigned d = (__float_as_uint(f) >> 19) - 0x800u;
                    if (d > D) orow[s_col[i]] = f;
                }
                // bin-D: exact top-m by (value desc, index asc) == jax tie order
                const unsigned ne = s_ecnt;
                const unsigned m  = s_m;
                if (tid < 32) {
                    for (unsigned i = (unsigned)lane; i < ne; i += 32u) {
                        const unsigned bi = __float_as_uint(e_val[i]);
                        const unsigned ci = e_col[i];
                        unsigned rank = 0;
                        for (unsigned jj = 0; jj < ne; jj++) {
                            const unsigned bj = __float_as_uint(e_val[jj]);
                            const unsigned cj = e_col[jj];
                            rank += (unsigned)((bj > bi) || (bj == bi && cj < ci));
                        }
                        if (rank < m) orow[ci] = e_val[i];
                    }
                }
                done = true;
            }
        }

        if (!done) {
            // ---- generic exact fallback (statistically never taken) ----
            const int kk = (K < COLS) ? K : COLS;
            if (kk > 0) {
                auto count_ge = [&](unsigned t) -> unsigned {
                    unsigned c = 0;
                    for (int cc = 0; cc < NCHUNK_G; cc++) {
                        const float4 v = xv[cc * NT + tid];
                        #pragma unroll
                        for (int e = 0; e < 4; e++) {
                            const float f = (e == 0) ? v.x : (e == 1) ? v.y : (e == 2) ? v.z : v.w;
                            const int   b = __float_as_int(f);
                            const unsigned key = (b > 0) ? (unsigned)b : 0u;
                            c += (unsigned)(key >= t);
                        }
                    }
                    return block_reduce_sum(c, s_red);
                };

                const unsigned cpos = count_ge(1u);
                if (cpos <= (unsigned)kk) {
                    for (int cc = 0; cc < NCHUNK_G; cc++) {
                        const int idx = cc * NT + tid;
                        const float4 v = xv[idx];
                        #pragma unroll
                        for (int e = 0; e < 4; e++) {
                            const float f = (e == 0) ? v.x : (e == 1) ? v.y : (e == 2) ? v.z : v.w;
                            if (__float_as_int(f) > 0) orow[idx * 4 + e] = f;
                        }
                    }
                } else {
                    unsigned lo = 1u, hi2 = 0x7F800000u;
                    while (hi2 - lo > 1u) {
                        const unsigned mid = lo + (hi2 - lo) / 2u;
                        if (count_ge(mid) >= (unsigned)kk) lo = mid; else hi2 = mid;
                    }
                    const unsigned T = lo;
                    const unsigned gcnt = count_ge(T + 1u);
                    const unsigned m = (unsigned)kk - gcnt;

                    if (tid == 0) s_ecnt = 0u;
                    __syncthreads();
                    for (int cc = 0; cc < NCHUNK_G; cc++) {
                        const int idx = cc * NT + tid;
                        const float4 v = xv[idx];
                        #pragma unroll
                        for (int e = 0; e < 4; e++) {
                            const float f = (e == 0) ? v.x : (e == 1) ? v.y : (e == 2) ? v.z : v.w;
                            const int   b = __float_as_int(f);
                            const unsigned key = (b > 0) ? (unsigned)b : 0u;
                            if (key > T) orow[idx * 4 + e] = f;
                            else if (key == T) {
                                const unsigned p = atomicAdd(&s_ecnt, 1u);
                                if (p < ECAP) { e_val[p] = f; e_col[p] = (unsigned short)(idx * 4 + e); }
                            }
                        }
                    }
                    __syncthreads();
                    const unsigned ne = (s_ecnt < ECAP) ? s_ecnt : ECAP;
                    if (tid < 32) {
                        for (unsigned i = (unsigned)lane; i < ne; i += 32u) {
                            const unsigned ci = e_col[i];
                            unsigned rank = 0;
                            for (unsigned jj = 0; jj < ne; jj++) rank += (unsigned)(e_col[jj] < ci);
                            if (rank < m) orow[ci] = e_val[i];
                        }
                    }
                }
            }
        }
        __syncthreads();   // selection fully done before next row's init overwrites shared state
    }
}

extern "C" void kernel_launch(void* const* d_in, const int* in_sizes, int n_in,
                              void* d_out, int out_size)
{
    const float* x = (const float*)d_in[0];
    const int*   k = (const int*)d_in[1];
    float*       o = (float*)d_out;
    const int rows = in_sizes[0] / COLS;

    cudaFuncSetAttribute(topk_rows_kernel, cudaFuncAttributeMaxDynamicSharedMemorySize, DYN_SMEM);
    const int grid = rows < 304 ? rows : 304;   // 2 persistent CTAs per SM (152 SMs)
    topk_rows_kernel<<<grid, NT, DYN_SMEM>>>(x, k, o, rows);
}